// round 3
// baseline (speedup 1.0000x reference)
#include <cuda_runtime.h>

// E90 dual-rate gated linear-attention scan — barrier-free warp-local design.
// T=2048, B=8, H=16, KF=32, VF=64, KS=128, VS=64. 128 CTAs (one per b,h),
// 256 threads. Warp w owns output columns [8w, 8w+8). Lane (rg=l>>2, cp=l&3)
// owns 2 columns (8w+2cp, 8w+2cp+1) x 20 rows (4 fast + 16 slow), held as
// packed f32x2 registers with ROWS in the pair dimension, so k/q arrive
// pre-packed from ulonglong2 global loads. No shared memory, no __syncthreads
// in the main loop; q-dot reduced with 3 warp shuffles per step.

#define T_DIM 2048
#define BH    128
#define KF    32
#define VF    64
#define KS    128
#define VS    64

typedef unsigned long long u64;

__device__ __forceinline__ u64 pack2(float x, float y) {
    u64 u; asm("mov.b64 %0, {%1,%2};" : "=l"(u) : "f"(x), "f"(y)); return u;
}
__device__ __forceinline__ void unpack2(u64 u, float& x, float& y) {
    asm("mov.b64 {%0,%1}, %2;" : "=f"(x), "=f"(y) : "l"(u));
}
__device__ __forceinline__ u64 dup2(float x) { return pack2(x, x); }
__device__ __forceinline__ u64 ffma2(u64 a, u64 b, u64 c) {
    u64 d; asm("fma.rn.f32x2 %0, %1, %2, %3;" : "=l"(d) : "l"(a), "l"(b), "l"(c)); return d;
}
__device__ __forceinline__ u64 fmul2(u64 a, u64 b) {
    u64 d; asm("mul.rn.f32x2 %0, %1, %2;" : "=l"(d) : "l"(a), "l"(b)); return d;
}
__device__ __forceinline__ u64 fadd2(u64 a, u64 b) {
    u64 d; asm("add.rn.f32x2 %0, %1, %2;" : "=l"(d) : "l"(a), "l"(b)); return d;
}
__device__ __forceinline__ u64 shfl_xor_u64(u64 v, int m) {
    double d = __longlong_as_double((long long)v);
    d = __shfl_xor_sync(0xffffffffu, d, m);
    return (u64)__double_as_longlong(d);
}

// ---- prefetch pieces for step index TT into slot S ----
#define PF_SCV(S, TT) do { size_t _t = (size_t)(TT);                           \
    bdf[S] = __ldg(df_p + _t * BH);  bds[S] = __ldg(ds_p + _t * BH);           \
    bg[S]  = __ldg(g_p  + _t * BH);  bmf[S] = __ldg(mf_p + _t * BH);           \
    bms[S] = __ldg(ms_p + _t * BH);                                            \
    bvf[S] = __ldg(vf_p + _t * (BH * VF / 2));                                 \
    bvs[S] = __ldg(vs_p + _t * (BH * VS / 2)); } while (0)

#define PF_FAST(S, TT) do { size_t _t = (size_t)(TT);                          \
    bkf[S] = __ldg(kf_p + _t * (BH * KF / 4));                                 \
    bqf[S] = __ldg(qf_p + _t * (BH * KF / 4)); } while (0)

#define PF_SLOW(S, TT) do { size_t _t = (size_t)(TT);                          \
    bks[S][0] = __ldg(ks_p + _t * (BH * KS / 4) + 0);                          \
    bks[S][1] = __ldg(ks_p + _t * (BH * KS / 4) + 1);                          \
    bks[S][2] = __ldg(ks_p + _t * (BH * KS / 4) + 2);                          \
    bks[S][3] = __ldg(ks_p + _t * (BH * KS / 4) + 3);                          \
    bqs[S][0] = __ldg(qs_p + _t * (BH * KS / 4) + 0);                          \
    bqs[S][1] = __ldg(qs_p + _t * (BH * KS / 4) + 1);                          \
    bqs[S][2] = __ldg(qs_p + _t * (BH * KS / 4) + 2);                          \
    bqs[S][3] = __ldg(qs_p + _t * (BH * KS / 4) + 3); } while (0)

// ---- one scan step. S = t&1. Prefetches t+2 into slot S after each buffer's
// last use (register double-buffer, ~2-iteration latency cover, no barriers).
#define ITER(TCUR, S) do {                                                     \
    const int _tp = ((TCUR) + 2 < T_DIM) ? (TCUR) + 2 : T_DIM - 1;             \
    float df_ = bdf[S], ds_ = bds[S], g_ = bg[S], mf_ = bmf[S], ms_ = bms[S];  \
    float2 vf_ = bvf[S], vs_ = bvs[S];                                         \
    u64 d2f = dup2(df_);                                                       \
    u64 d2s = dup2(fmaf(g_, ds_ - 1.0f, 1.0f));                                \
    u64 vf0 = dup2(vf_.x), vf1 = dup2(vf_.y);                                  \
    u64 vs0 = dup2(g_ * vs_.x), vs1 = dup2(g_ * vs_.y);                        \
    PF_SCV(S, _tp);                                                            \
    /* fast state: 4 pairs */                                                  \
    u64 kf0 = bkf[S].x, kf1 = bkf[S].y, qf0 = bqf[S].x, qf1 = bqf[S].y;        \
    PF_FAST(S, _tp);                                                           \
    Sf[0] = ffma2(d2f, Sf[0], fmul2(kf0, vf0));                                \
    u64 af0 = fmul2(qf0, Sf[0]);                                               \
    Sf[1] = ffma2(d2f, Sf[1], fmul2(kf1, vf0));                                \
    af0 = ffma2(qf1, Sf[1], af0);                                              \
    Sf[2] = ffma2(d2f, Sf[2], fmul2(kf0, vf1));                                \
    u64 af1 = fmul2(qf0, Sf[2]);                                               \
    Sf[3] = ffma2(d2f, Sf[3], fmul2(kf1, vf1));                                \
    af1 = ffma2(qf1, Sf[3], af1);                                              \
    /* slow state: 16 pairs, read k/q pairs straight from buffers */           \
    u64 as0, as1;                                                              \
    Ss[0] = ffma2(d2s, Ss[0], fmul2(bks[S][0].x, vs0));                        \
    as0 = fmul2(bqs[S][0].x, Ss[0]);                                           \
    Ss[1] = ffma2(d2s, Ss[1], fmul2(bks[S][0].y, vs0));                        \
    as0 = ffma2(bqs[S][0].y, Ss[1], as0);                                      \
    Ss[2] = ffma2(d2s, Ss[2], fmul2(bks[S][1].x, vs0));                        \
    as0 = ffma2(bqs[S][1].x, Ss[2], as0);                                      \
    Ss[3] = ffma2(d2s, Ss[3], fmul2(bks[S][1].y, vs0));                        \
    as0 = ffma2(bqs[S][1].y, Ss[3], as0);                                      \
    Ss[4] = ffma2(d2s, Ss[4], fmul2(bks[S][2].x, vs0));                        \
    as0 = ffma2(bqs[S][2].x, Ss[4], as0);                                      \
    Ss[5] = ffma2(d2s, Ss[5], fmul2(bks[S][2].y, vs0));                        \
    as0 = ffma2(bqs[S][2].y, Ss[5], as0);                                      \
    Ss[6] = ffma2(d2s, Ss[6], fmul2(bks[S][3].x, vs0));                        \
    as0 = ffma2(bqs[S][3].x, Ss[6], as0);                                      \
    Ss[7] = ffma2(d2s, Ss[7], fmul2(bks[S][3].y, vs0));                        \
    as0 = ffma2(bqs[S][3].y, Ss[7], as0);                                      \
    Ss[8]  = ffma2(d2s, Ss[8],  fmul2(bks[S][0].x, vs1));                      \
    as1 = fmul2(bqs[S][0].x, Ss[8]);                                           \
    Ss[9]  = ffma2(d2s, Ss[9],  fmul2(bks[S][0].y, vs1));                      \
    as1 = ffma2(bqs[S][0].y, Ss[9], as1);                                      \
    Ss[10] = ffma2(d2s, Ss[10], fmul2(bks[S][1].x, vs1));                      \
    as1 = ffma2(bqs[S][1].x, Ss[10], as1);                                     \
    Ss[11] = ffma2(d2s, Ss[11], fmul2(bks[S][1].y, vs1));                      \
    as1 = ffma2(bqs[S][1].y, Ss[11], as1);                                     \
    Ss[12] = ffma2(d2s, Ss[12], fmul2(bks[S][2].x, vs1));                      \
    as1 = ffma2(bqs[S][2].x, Ss[12], as1);                                     \
    Ss[13] = ffma2(d2s, Ss[13], fmul2(bks[S][2].y, vs1));                      \
    as1 = ffma2(bqs[S][2].y, Ss[13], as1);                                     \
    Ss[14] = ffma2(d2s, Ss[14], fmul2(bks[S][3].x, vs1));                      \
    as1 = ffma2(bqs[S][3].x, Ss[14], as1);                                     \
    Ss[15] = ffma2(d2s, Ss[15], fmul2(bks[S][3].y, vs1));                      \
    as1 = ffma2(bqs[S][3].y, Ss[15], as1);                                     \
    PF_SLOW(S, _tp);                                                           \
    /* horizontal (row pairs) + mix + warp reduce over 8 rowgroups */          \
    float _a, _b, yf0, yf1, ys0, ys1;                                          \
    unpack2(af0, _a, _b); yf0 = _a + _b;                                       \
    unpack2(af1, _a, _b); yf1 = _a + _b;                                       \
    unpack2(as0, _a, _b); ys0 = _a + _b;                                       \
    unpack2(as1, _a, _b); ys1 = _a + _b;                                       \
    u64 y2 = pack2(fmaf(ms_, ys0, mf_ * yf0), fmaf(ms_, ys1, mf_ * yf1));      \
    y2 = fadd2(y2, shfl_xor_u64(y2, 4));                                       \
    y2 = fadd2(y2, shfl_xor_u64(y2, 8));                                       \
    y2 = fadd2(y2, shfl_xor_u64(y2, 16));                                      \
    if (rg == 0)                                                               \
        ((u64*)out_y)[((size_t)(TCUR) * BH + bh) * (VF / 2) + w * 4 + cp] = y2;\
} while (0)

__global__ void __launch_bounds__(256, 1)
e90_dualrate_kernel(const float* __restrict__ k_fast,
                    const float* __restrict__ v_fast,
                    const float* __restrict__ q_fast,
                    const float* __restrict__ decay_fast,
                    const float* __restrict__ k_slow,
                    const float* __restrict__ v_slow,
                    const float* __restrict__ q_slow,
                    const float* __restrict__ decay_slow,
                    const float* __restrict__ slow_gate,
                    const float* __restrict__ mix_fast,
                    const float* __restrict__ mix_slow,
                    const float* __restrict__ S_fast0,
                    const float* __restrict__ S_slow0,
                    float* __restrict__ out_Sf,   // may be null
                    float* __restrict__ out_Ss,   // may be null
                    float* __restrict__ out_y) {
    const int tid = threadIdx.x;
    const int w   = tid >> 5;        // warp: owns columns [8w, 8w+8)
    const int l   = tid & 31;
    const int rg  = l >> 2;          // row group 0..7
    const int cp  = l & 3;           // column pair 0..3
    const int bh  = blockIdx.x;
    const int c0  = w * 8 + 2 * cp;  // lane's first column

    // per-lane base pointers (vectorized units)
    const ulonglong2* kf_p = (const ulonglong2*)k_fast + (size_t)bh * (KF / 4) + rg;
    const ulonglong2* qf_p = (const ulonglong2*)q_fast + (size_t)bh * (KF / 4) + rg;
    const ulonglong2* ks_p = (const ulonglong2*)k_slow + (size_t)bh * (KS / 4) + rg * 4;
    const ulonglong2* qs_p = (const ulonglong2*)q_slow + (size_t)bh * (KS / 4) + rg * 4;
    const float2*     vf_p = (const float2*)v_fast + (size_t)bh * (VF / 2) + (w * 4 + cp);
    const float2*     vs_p = (const float2*)v_slow + (size_t)bh * (VS / 2) + (w * 4 + cp);
    const float*      df_p = decay_fast + bh;
    const float*      ds_p = decay_slow + bh;
    const float*      g_p  = slow_gate + bh;
    const float*      mf_p = mix_fast + bh;
    const float*      ms_p = mix_slow + bh;

    // double-buffered prefetch registers
    ulonglong2 bkf[2], bqf[2], bks[2][4], bqs[2][4];
    float2 bvf[2], bvs[2];
    float bdf[2], bds[2], bg[2], bmf[2], bms[2];

    // register states: Sf[c*2+i] = rows (rg*4+2i, +1), col c0+c
    //                  Ss[c*8+j] = rows (rg*16+2j, +1), col c0+c
    u64 Sf[4], Ss[16];
#pragma unroll
    for (int c = 0; c < 2; c++)
#pragma unroll
        for (int i = 0; i < 2; i++) {
            size_t r = (size_t)rg * 4 + 2 * i;
            Sf[c * 2 + i] = pack2(S_fast0[((size_t)bh * KF + r) * VF + c0 + c],
                                  S_fast0[((size_t)bh * KF + r + 1) * VF + c0 + c]);
        }
#pragma unroll
    for (int c = 0; c < 2; c++)
#pragma unroll
        for (int j = 0; j < 8; j++) {
            size_t r = (size_t)rg * 16 + 2 * j;
            Ss[c * 8 + j] = pack2(S_slow0[((size_t)bh * KS + r) * VS + c0 + c],
                                  S_slow0[((size_t)bh * KS + r + 1) * VS + c0 + c]);
        }

    // prologue prefetch: t=0 -> slot 0, t=1 -> slot 1
    PF_SCV(0, 0); PF_FAST(0, 0); PF_SLOW(0, 0);
    PF_SCV(1, 1); PF_FAST(1, 1); PF_SLOW(1, 1);

    for (int t = 0; t < T_DIM; t += 2) {
        ITER(t, 0);
        ITER(t + 1, 1);
    }

    // final states
    float a, b;
    if (out_Sf) {
#pragma unroll
        for (int c = 0; c < 2; c++)
#pragma unroll
            for (int i = 0; i < 2; i++) {
                size_t r = (size_t)rg * 4 + 2 * i;
                unpack2(Sf[c * 2 + i], a, b);
                out_Sf[((size_t)bh * KF + r) * VF + c0 + c] = a;
                out_Sf[((size_t)bh * KF + r + 1) * VF + c0 + c] = b;
            }
    }
    if (out_Ss) {
#pragma unroll
        for (int c = 0; c < 2; c++)
#pragma unroll
            for (int j = 0; j < 8; j++) {
                size_t r = (size_t)rg * 16 + 2 * j;
                unpack2(Ss[c * 8 + j], a, b);
                out_Ss[((size_t)bh * KS + r) * VS + c0 + c] = a;
                out_Ss[((size_t)bh * KS + r + 1) * VS + c0 + c] = b;
            }
    }
}

extern "C" void kernel_launch(void* const* d_in, const int* in_sizes, int n_in,
                              void* d_out, int out_size) {
    const float* k_fast     = (const float*)d_in[0];
    const float* v_fast     = (const float*)d_in[1];
    const float* q_fast     = (const float*)d_in[2];
    const float* decay_fast = (const float*)d_in[3];
    const float* k_slow     = (const float*)d_in[4];
    const float* v_slow     = (const float*)d_in[5];
    const float* q_slow     = (const float*)d_in[6];
    const float* decay_slow = (const float*)d_in[7];
    const float* slow_gate  = (const float*)d_in[8];
    const float* mix_fast   = (const float*)d_in[9];
    const float* mix_slow   = (const float*)d_in[10];
    const float* S_fast0    = (const float*)d_in[11];
    const float* S_slow0    = (const float*)d_in[12];

    float* out = (float*)d_out;
    const int sf_n = BH * KF * VF;
    const int ss_n = BH * KS * VS;
    const int y_n  = T_DIM * BH * VF;

    float *oSf, *oSs, *oY;
    if (out_size >= sf_n + ss_n + y_n) {
        oSf = out;
        oSs = out + sf_n;
        oY  = out + sf_n + ss_n;
    } else {
        oSf = nullptr;
        oSs = nullptr;
        oY  = out;
    }

    e90_dualrate_kernel<<<BH, 256>>>(k_fast, v_fast, q_fast, decay_fast,
                                     k_slow, v_slow, q_slow, decay_slow,
                                     slow_gate, mix_fast, mix_slow,
                                     S_fast0, S_slow0,
                                     oSf, oSs, oY);
}